// round 1
// baseline (speedup 1.0000x reference)
#include <cuda_runtime.h>
#include <math.h>

#define B_ 2
#define L_ 2048
#define V_ 1024
#define H_ 16
#define D_ 64
#define M_ (B_*L_)      // 4096 rows over (b, l)
#define STRIDE 68       // smem row stride (floats): 16B-aligned, bank-friendly

// Scratch (allocation-free rule: __device__ globals)
__device__ float g_Q[(size_t)B_*H_*L_*D_];
__device__ float g_K[(size_t)B_*H_*L_*D_];
__device__ float g_V[(size_t)B_*H_*L_*D_];
__device__ float g_X[(size_t)B_*L_*V_];

// ---------------------------------------------------------------------------
// Projection GEMM: C[b,h,l,d] = sum_v A[b,l,v] * W[h,v,d]
// A: (M_, V_) row-major. W: (H, V, D). C stored as (B,H,L,D).
// Classic 128x128 tile, 8x8 per thread, BK=8.
// ---------------------------------------------------------------------------
__global__ __launch_bounds__(256) void proj_gemm(const float* __restrict__ A,
                                                 const float* __restrict__ W,
                                                 float* __restrict__ C) {
  __shared__ float As[8][132];   // [k][m], padded
  __shared__ float Bs[8][128];   // [k][n]
  const int tid = threadIdx.x;
  const int m0 = blockIdx.x * 128;
  const int n0 = blockIdx.y * 128;
  const int la_r = tid >> 1;           // 0..127
  const int la_c = (tid & 1) * 4;      // 0 or 4
  const int lb_r = tid >> 5;           // 0..7
  const int lb_c = (tid & 31) * 4;     // 0..124
  const int ty = tid >> 4, tx = tid & 15;

  float acc[8][8];
#pragma unroll
  for (int i = 0; i < 8; i++)
#pragma unroll
    for (int j = 0; j < 8; j++) acc[i][j] = 0.f;

  const int nb = n0 + lb_c;
  const int hB = nb >> 6, dB = nb & 63;
  const float* Ag = A + (size_t)(m0 + la_r) * V_ + la_c;
  const float* Wg = W + (size_t)hB * (V_ * D_) + (size_t)lb_r * D_ + dB;

  for (int k0 = 0; k0 < V_; k0 += 8) {
    float4 av = *(const float4*)(Ag + k0);
    float4 bv = *(const float4*)(Wg + (size_t)k0 * D_);
    __syncthreads();
    As[la_c + 0][la_r] = av.x;
    As[la_c + 1][la_r] = av.y;
    As[la_c + 2][la_r] = av.z;
    As[la_c + 3][la_r] = av.w;
    *(float4*)&Bs[lb_r][lb_c] = bv;
    __syncthreads();
#pragma unroll
    for (int k = 0; k < 8; k++) {
      float a[8], b[8];
      *(float4*)&a[0] = *(const float4*)&As[k][ty * 8];
      *(float4*)&a[4] = *(const float4*)&As[k][ty * 8 + 4];
      *(float4*)&b[0] = *(const float4*)&Bs[k][tx * 8];
      *(float4*)&b[4] = *(const float4*)&Bs[k][tx * 8 + 4];
#pragma unroll
      for (int i = 0; i < 8; i++)
#pragma unroll
        for (int j = 0; j < 8; j++) acc[i][j] = fmaf(a[i], b[j], acc[i][j]);
    }
  }
#pragma unroll
  for (int i = 0; i < 8; i++) {
    int m = m0 + ty * 8 + i;
    int b = m >> 11, l = m & (L_ - 1);
#pragma unroll
    for (int j = 0; j < 8; j += 4) {
      int n = n0 + tx * 8 + j;
      int h = n >> 6, d = n & 63;
      float4 v = make_float4(acc[i][j], acc[i][j + 1], acc[i][j + 2], acc[i][j + 3]);
      *(float4*)&C[(((size_t)(b * H_ + h)) * L_ + l) * D_ + d] = v;
    }
  }
}

// ---------------------------------------------------------------------------
// Flash-style attention with FULL-ROW softmax denominator (reference applies
// softmax before the causal/tril mask), masks multiply the numerator only.
// One block = 64 query rows of one (b,h). 256 threads, 4x4 frags (16x16 grid).
// ---------------------------------------------------------------------------
__global__ __launch_bounds__(256) void flash_attn(
    const float* __restrict__ Qg, const float* __restrict__ Kg,
    const float* __restrict__ Vg, const float* __restrict__ qmask,
    const float* __restrict__ vmask, float* __restrict__ Xg) {
  extern __shared__ float sm[];
  float* Qs = sm;                  // [64][STRIDE] natural (r,d), pre-scaled
  float* Kt = Qs + 64 * STRIDE;    // [64][STRIDE] transposed (d,c)
  float* Vs = Kt + 64 * STRIDE;    // [64][STRIDE] natural (j,d)
  float* Ps = Vs + 64 * STRIDE;    // [64][STRIDE] natural (r,j)

  const int bh = blockIdx.y;
  const int b = bh >> 4;           // / H_
  const int h = bh & 15;
  const int qt = blockIdx.x;
  const int i0 = qt * 64;
  const int tid = threadIdx.x;
  const int ty = tid >> 4, tx = tid & 15;

  const float* Qb = Qg + (size_t)bh * (L_ * D_);
  const float* Kb = Kg + (size_t)bh * (L_ * D_);
  const float* Vb = Vg + (size_t)bh * (L_ * D_);

  for (int idx = tid; idx < 64 * 64; idx += 256) {
    int r = idx >> 6, d = idx & 63;
    Qs[r * STRIDE + d] = Qb[(size_t)(i0 + r) * D_ + d] * 0.125f;  // 1/sqrt(64)
  }

  float m_i[4], Zr[4], O[4][4];
#pragma unroll
  for (int i = 0; i < 4; i++) {
    m_i[i] = -1e30f; Zr[i] = 0.f;
#pragma unroll
    for (int j = 0; j < 4; j++) O[i][j] = 0.f;
  }

  for (int jt = 0; jt < L_ / 64; jt++) {
    const int j0 = jt * 64;
    const bool pv = (jt <= qt);
    __syncthreads();
    for (int idx = tid; idx < 64 * 64; idx += 256) {
      int r = idx >> 6, d = idx & 63;
      Kt[d * STRIDE + r] = Kb[(size_t)(j0 + r) * D_ + d];
      if (pv) Vs[r * STRIDE + d] = Vb[(size_t)(j0 + r) * D_ + d];
    }
    __syncthreads();

    float s[4][4];
#pragma unroll
    for (int i = 0; i < 4; i++)
#pragma unroll
      for (int j = 0; j < 4; j++) s[i][j] = 0.f;

#pragma unroll 8
    for (int d = 0; d < 64; d++) {
      float a0 = Qs[(ty * 4 + 0) * STRIDE + d];
      float a1 = Qs[(ty * 4 + 1) * STRIDE + d];
      float a2 = Qs[(ty * 4 + 2) * STRIDE + d];
      float a3 = Qs[(ty * 4 + 3) * STRIDE + d];
      float4 bv = *(const float4*)&Kt[d * STRIDE + tx * 4];
      s[0][0] = fmaf(a0, bv.x, s[0][0]); s[0][1] = fmaf(a0, bv.y, s[0][1]);
      s[0][2] = fmaf(a0, bv.z, s[0][2]); s[0][3] = fmaf(a0, bv.w, s[0][3]);
      s[1][0] = fmaf(a1, bv.x, s[1][0]); s[1][1] = fmaf(a1, bv.y, s[1][1]);
      s[1][2] = fmaf(a1, bv.z, s[1][2]); s[1][3] = fmaf(a1, bv.w, s[1][3]);
      s[2][0] = fmaf(a2, bv.x, s[2][0]); s[2][1] = fmaf(a2, bv.y, s[2][1]);
      s[2][2] = fmaf(a2, bv.z, s[2][2]); s[2][3] = fmaf(a2, bv.w, s[2][3]);
      s[3][0] = fmaf(a3, bv.x, s[3][0]); s[3][1] = fmaf(a3, bv.y, s[3][1]);
      s[3][2] = fmaf(a3, bv.z, s[3][2]); s[3][3] = fmaf(a3, bv.w, s[3][3]);
    }

    // Online softmax stats over ALL columns (full-row denominator)
#pragma unroll
    for (int i = 0; i < 4; i++) {
      float tm = fmaxf(fmaxf(s[i][0], s[i][1]), fmaxf(s[i][2], s[i][3]));
#pragma unroll
      for (int o = 8; o; o >>= 1) tm = fmaxf(tm, __shfl_xor_sync(0xffffffffu, tm, o));
      float nm = fmaxf(m_i[i], tm);
      float corr = __expf(m_i[i] - nm);
      m_i[i] = nm;
      float ts = 0.f;
#pragma unroll
      for (int j = 0; j < 4; j++) {
        float p = __expf(s[i][j] - nm);
        s[i][j] = p;
        ts += p;
      }
#pragma unroll
      for (int o = 8; o; o >>= 1) ts += __shfl_xor_sync(0xffffffffu, ts, o);
      Zr[i] = Zr[i] * corr + ts;
#pragma unroll
      for (int j = 0; j < 4; j++) O[i][j] *= corr;
    }

    if (pv) {  // only causal tiles contribute to O (numerator masked)
#pragma unroll
      for (int i = 0; i < 4; i++) {
        int gi = i0 + ty * 4 + i;
#pragma unroll
        for (int j = 0; j < 4; j++) {
          int gj = j0 + tx * 4 + j;
          s[i][j] = (gj <= gi) ? s[i][j] * vmask[b * L_ + gj] : 0.f;
        }
        *(float4*)&Ps[(ty * 4 + i) * STRIDE + tx * 4] =
            make_float4(s[i][0], s[i][1], s[i][2], s[i][3]);
      }
      __syncthreads();
#pragma unroll 8
      for (int j = 0; j < 64; j++) {
        float a0 = Ps[(ty * 4 + 0) * STRIDE + j];
        float a1 = Ps[(ty * 4 + 1) * STRIDE + j];
        float a2 = Ps[(ty * 4 + 2) * STRIDE + j];
        float a3 = Ps[(ty * 4 + 3) * STRIDE + j];
        float4 bv = *(const float4*)&Vs[j * STRIDE + tx * 4];
        O[0][0] = fmaf(a0, bv.x, O[0][0]); O[0][1] = fmaf(a0, bv.y, O[0][1]);
        O[0][2] = fmaf(a0, bv.z, O[0][2]); O[0][3] = fmaf(a0, bv.w, O[0][3]);
        O[1][0] = fmaf(a1, bv.x, O[1][0]); O[1][1] = fmaf(a1, bv.y, O[1][1]);
        O[1][2] = fmaf(a1, bv.z, O[1][2]); O[1][3] = fmaf(a1, bv.w, O[1][3]);
        O[2][0] = fmaf(a2, bv.x, O[2][0]); O[2][1] = fmaf(a2, bv.y, O[2][1]);
        O[2][2] = fmaf(a2, bv.z, O[2][2]); O[2][3] = fmaf(a2, bv.w, O[2][3]);
        O[3][0] = fmaf(a3, bv.x, O[3][0]); O[3][1] = fmaf(a3, bv.y, O[3][1]);
        O[3][2] = fmaf(a3, bv.z, O[3][2]); O[3][3] = fmaf(a3, bv.w, O[3][3]);
      }
    }
  }

  // Epilogue: out[b,l,h,d] = qmask * O / Z  (concat-heads layout == (B,L,V))
#pragma unroll
  for (int i = 0; i < 4; i++) {
    int gi = i0 + ty * 4 + i;
    float f = qmask[b * L_ + gi] / Zr[i];
    float4 v = make_float4(O[i][0] * f, O[i][1] * f, O[i][2] * f, O[i][3] * f);
    *(float4*)&Xg[((size_t)(b * L_ + gi) * H_ + h) * D_ + tx * 4] = v;
  }
}

// ---------------------------------------------------------------------------
// Residual add + LayerNorm over last dim (V=1024). One block per row.
// ---------------------------------------------------------------------------
__global__ __launch_bounds__(256) void add_ln(const float* __restrict__ X,
                                              const float* __restrict__ Qin,
                                              const float* __restrict__ gamma,
                                              const float* __restrict__ beta,
                                              float* __restrict__ out) {
  __shared__ float red[16];
  __shared__ float s_mean, s_rstd;
  const int row = blockIdx.x;
  const int t = threadIdx.x;
  const float4 xv = ((const float4*)(X + (size_t)row * V_))[t];
  const float4 qv = ((const float4*)(Qin + (size_t)row * V_))[t];
  float4 y = make_float4(xv.x + qv.x, xv.y + qv.y, xv.z + qv.z, xv.w + qv.w);
  float s = y.x + y.y + y.z + y.w;
  float ss = y.x * y.x + y.y * y.y + y.z * y.z + y.w * y.w;
#pragma unroll
  for (int o = 16; o; o >>= 1) {
    s += __shfl_xor_sync(0xffffffffu, s, o);
    ss += __shfl_xor_sync(0xffffffffu, ss, o);
  }
  if ((t & 31) == 0) { red[t >> 5] = s; red[8 + (t >> 5)] = ss; }
  __syncthreads();
  if (t < 32) {
    float s2 = (t < 8) ? red[t] : 0.f;
    float ss2 = (t < 8) ? red[8 + t] : 0.f;
#pragma unroll
    for (int o = 4; o; o >>= 1) {
      s2 += __shfl_xor_sync(0xffffffffu, s2, o);
      ss2 += __shfl_xor_sync(0xffffffffu, ss2, o);
    }
    if (t == 0) {
      float mean = s2 * (1.f / V_);
      float var = ss2 * (1.f / V_) - mean * mean;
      s_mean = mean;
      s_rstd = rsqrtf(var + 1e-3f);
    }
  }
  __syncthreads();
  float mean = s_mean, r = s_rstd;
  float4 g = ((const float4*)gamma)[t];
  float4 be = ((const float4*)beta)[t];
  float4 o4 = make_float4((y.x - mean) * r * g.x + be.x,
                          (y.y - mean) * r * g.y + be.y,
                          (y.z - mean) * r * g.z + be.z,
                          (y.w - mean) * r * g.w + be.w);
  ((float4*)(out + (size_t)row * V_))[t] = o4;
}

// ---------------------------------------------------------------------------
extern "C" void kernel_launch(void* const* d_in, const int* in_sizes, int n_in,
                              void* d_out, int out_size) {
  (void)in_sizes; (void)n_in; (void)out_size;
  const float* query = (const float*)d_in[0];
  const float* key   = (const float*)d_in[1];
  const float* value = (const float*)d_in[2];
  const float* qmask = (const float*)d_in[3];
  const float* vmask = (const float*)d_in[4];
  const float* Wq    = (const float*)d_in[5];
  const float* Wk    = (const float*)d_in[6];
  const float* Wv    = (const float*)d_in[7];
  const float* gamma = (const float*)d_in[8];
  const float* beta  = (const float*)d_in[9];
  float* out = (float*)d_out;

  float *gQ, *gK, *gV, *gX;
  cudaGetSymbolAddress((void**)&gQ, g_Q);
  cudaGetSymbolAddress((void**)&gK, g_K);
  cudaGetSymbolAddress((void**)&gV, g_V);
  cudaGetSymbolAddress((void**)&gX, g_X);

  const size_t fa_smem = (size_t)4 * 64 * STRIDE * sizeof(float);  // 69632 B
  cudaFuncSetAttribute(flash_attn, cudaFuncAttributeMaxDynamicSharedMemorySize,
                       (int)fa_smem);

  dim3 gproj(M_ / 128, V_ / 128);  // 32 x 8
  proj_gemm<<<gproj, 256>>>(query, Wq, gQ);
  proj_gemm<<<gproj, 256>>>(key,   Wk, gK);
  proj_gemm<<<gproj, 256>>>(value, Wv, gV);

  dim3 gfa(L_ / 64, B_ * H_);      // 32 x 32
  flash_attn<<<gfa, 256, fa_smem>>>(gQ, gK, gV, qmask, vmask, gX);

  add_ln<<<M_, 256>>>(gX, query, gamma, beta, out);
}

// round 2
// speedup vs baseline: 1.0754x; 1.0754x over previous
#include <cuda_runtime.h>
#include <math.h>

#define B_ 2
#define L_ 2048
#define V_ 1024
#define H_ 16
#define D_ 64
#define M_ (B_*L_)

// flash tiling
#define BM 128
#define BN 64
#define QT_STRIDE 132
#define KT_STRIDE 68
#define VS_STRIDE 68
#define PS_STRIDE 68

// Scratch (allocation-free rule: __device__ globals)
__device__ float g_Q[(size_t)B_*H_*L_*D_];
__device__ float g_K[(size_t)B_*H_*L_*D_];
__device__ float g_V[(size_t)B_*H_*L_*D_];
__device__ float g_X[(size_t)B_*L_*V_];

// ---------------------------------------------------------------------------
// Projection GEMMs, all three in one launch (z = which projection).
// C[b,h,l,d] = sum_v A[b,l,v] * W[h,v,d]; A:(M_,V_), W:(H,V,D), C:(B,H,L,D).
// 128x128 tile, 8x8 per thread, BK=8.
// ---------------------------------------------------------------------------
__global__ __launch_bounds__(256) void proj_gemm3(
    const float* __restrict__ Aq, const float* __restrict__ Ak,
    const float* __restrict__ Av, const float* __restrict__ Wq,
    const float* __restrict__ Wk, const float* __restrict__ Wv,
    float* __restrict__ Cq, float* __restrict__ Ck, float* __restrict__ Cv) {
  const int z = blockIdx.z;
  const float* A = (z == 0) ? Aq : (z == 1) ? Ak : Av;
  const float* W = (z == 0) ? Wq : (z == 1) ? Wk : Wv;
  float* C = (z == 0) ? Cq : (z == 1) ? Ck : Cv;

  __shared__ float As[8][132];
  __shared__ float Bs[8][128];
  const int tid = threadIdx.x;
  const int m0 = blockIdx.x * 128;
  const int n0 = blockIdx.y * 128;
  const int la_r = tid >> 1;
  const int la_c = (tid & 1) * 4;
  const int lb_r = tid >> 5;
  const int lb_c = (tid & 31) * 4;
  const int ty = tid >> 4, tx = tid & 15;

  float acc[8][8];
#pragma unroll
  for (int i = 0; i < 8; i++)
#pragma unroll
    for (int j = 0; j < 8; j++) acc[i][j] = 0.f;

  const int nb = n0 + lb_c;
  const int hB = nb >> 6, dB = nb & 63;
  const float* Ag = A + (size_t)(m0 + la_r) * V_ + la_c;
  const float* Wg = W + (size_t)hB * (V_ * D_) + (size_t)lb_r * D_ + dB;

  for (int k0 = 0; k0 < V_; k0 += 8) {
    float4 av = *(const float4*)(Ag + k0);
    float4 bv = *(const float4*)(Wg + (size_t)k0 * D_);
    __syncthreads();
    As[la_c + 0][la_r] = av.x;
    As[la_c + 1][la_r] = av.y;
    As[la_c + 2][la_r] = av.z;
    As[la_c + 3][la_r] = av.w;
    *(float4*)&Bs[lb_r][lb_c] = bv;
    __syncthreads();
#pragma unroll
    for (int k = 0; k < 8; k++) {
      float a[8], b[8];
      *(float4*)&a[0] = *(const float4*)&As[k][ty * 8];
      *(float4*)&a[4] = *(const float4*)&As[k][ty * 8 + 4];
      *(float4*)&b[0] = *(const float4*)&Bs[k][tx * 8];
      *(float4*)&b[4] = *(const float4*)&Bs[k][tx * 8 + 4];
#pragma unroll
      for (int i = 0; i < 8; i++)
#pragma unroll
        for (int j = 0; j < 8; j++) acc[i][j] = fmaf(a[i], b[j], acc[i][j]);
    }
  }
#pragma unroll
  for (int i = 0; i < 8; i++) {
    int m = m0 + ty * 8 + i;
    int b = m >> 11, l = m & (L_ - 1);
#pragma unroll
    for (int j = 0; j < 8; j += 4) {
      int n = n0 + tx * 8 + j;
      int h = n >> 6, d = n & 63;
      float4 v = make_float4(acc[i][j], acc[i][j + 1], acc[i][j + 2], acc[i][j + 3]);
      *(float4*)&C[(((size_t)(b * H_ + h)) * L_ + l) * D_ + d] = v;
    }
  }
}

// ---------------------------------------------------------------------------
// Flash attention, FULL-ROW softmax denominator (softmax before tril mask),
// masks multiply the numerator only. No online max (scores are O(1), exp is
// overflow-safe in fp32) -> Z accumulated per-thread, reduced once at end.
// 128 query rows x 64 KV cols per tile iter; 256 threads, 8x4 frags.
// ---------------------------------------------------------------------------
__global__ __launch_bounds__(256, 2) void flash_attn(
    const float* __restrict__ Qg, const float* __restrict__ Kg,
    const float* __restrict__ Vg, const float* __restrict__ qmask,
    const float* __restrict__ vmask, float* __restrict__ Xg) {
  extern __shared__ float sm[];
  float* Qt = sm;                        // [64][QT_STRIDE] (d, r), pre-scaled
  float* Kt = Qt + 64 * QT_STRIDE;       // [64][KT_STRIDE] (d, j)
  float* Vs = Kt + 64 * KT_STRIDE;       // [64][VS_STRIDE] (j, d)
  float* Ps = Vs + 64 * VS_STRIDE;       // [128][PS_STRIDE] (r, j)

  const int bh = blockIdx.y;
  const int b = bh >> 4;
  const int h = bh & 15;
  const int qt = blockIdx.x;
  const int i0 = qt * BM;
  const int tid = threadIdx.x;
  const int ty = tid >> 4, tx = tid & 15;

  const float* Qb = Qg + (size_t)bh * (L_ * D_);
  const float* Kb = Kg + (size_t)bh * (L_ * D_);
  const float* Vb = Vg + (size_t)bh * (L_ * D_);

  // Load Q tile transposed + scaled by 1/sqrt(D)
  for (int idx = tid; idx < BM * 16; idx += 256) {
    int r = idx >> 4, d4 = (idx & 15) * 4;
    float4 v = *(const float4*)&Qb[(size_t)(i0 + r) * D_ + d4];
    Qt[(d4 + 0) * QT_STRIDE + r] = v.x * 0.125f;
    Qt[(d4 + 1) * QT_STRIDE + r] = v.y * 0.125f;
    Qt[(d4 + 2) * QT_STRIDE + r] = v.z * 0.125f;
    Qt[(d4 + 3) * QT_STRIDE + r] = v.w * 0.125f;
  }

  float O[8][4], Zacc[8];
#pragma unroll
  for (int i = 0; i < 8; i++) {
    Zacc[i] = 0.f;
#pragma unroll
    for (int j = 0; j < 4; j++) O[i][j] = 0.f;
  }

  for (int jt = 0; jt < L_ / BN; jt++) {
    const int j0 = jt * BN;
    const bool pv = (jt <= 2 * qt + 1);          // tile intersects causal region
    const bool needchk = (jt >= 2 * qt);         // diagonal tiles need per-elem check
    __syncthreads();
    // Load K transposed
    for (int idx = tid; idx < BN * 16; idx += 256) {
      int j = idx >> 4, d4 = (idx & 15) * 4;
      float4 v = *(const float4*)&Kb[(size_t)(j0 + j) * D_ + d4];
      Kt[(d4 + 0) * KT_STRIDE + j] = v.x;
      Kt[(d4 + 1) * KT_STRIDE + j] = v.y;
      Kt[(d4 + 2) * KT_STRIDE + j] = v.z;
      Kt[(d4 + 3) * KT_STRIDE + j] = v.w;
    }
    if (pv) {
      for (int idx = tid; idx < BN * 16; idx += 256) {
        int j = idx >> 4, d4 = (idx & 15) * 4;
        *(float4*)&Vs[j * VS_STRIDE + d4] =
            *(const float4*)&Vb[(size_t)(j0 + j) * D_ + d4];
      }
    }
    __syncthreads();

    // S = Q K^T (tile)
    float s[8][4];
#pragma unroll
    for (int i = 0; i < 8; i++)
#pragma unroll
      for (int j = 0; j < 4; j++) s[i][j] = 0.f;

#pragma unroll 4
    for (int d = 0; d < 64; d++) {
      float a[8], bb[4];
      *(float4*)&a[0] = *(const float4*)&Qt[d * QT_STRIDE + ty * 8];
      *(float4*)&a[4] = *(const float4*)&Qt[d * QT_STRIDE + ty * 8 + 4];
      *(float4*)&bb[0] = *(const float4*)&Kt[d * KT_STRIDE + tx * 4];
#pragma unroll
      for (int i = 0; i < 8; i++)
#pragma unroll
        for (int j = 0; j < 4; j++) s[i][j] = fmaf(a[i], bb[j], s[i][j]);
    }

    // exp + denominator accumulation (ALL columns count toward Z)
#pragma unroll
    for (int i = 0; i < 8; i++)
#pragma unroll
      for (int j = 0; j < 4; j++) {
        float p = __expf(s[i][j]);
        s[i][j] = p;
        Zacc[i] += p;
      }

    if (pv) {
      float vm[4];
#pragma unroll
      for (int j = 0; j < 4; j++) vm[j] = vmask[b * L_ + j0 + tx * 4 + j];
      if (needchk) {
#pragma unroll
        for (int i = 0; i < 8; i++) {
          int gi = i0 + ty * 8 + i;
#pragma unroll
          for (int j = 0; j < 4; j++) {
            int gj = j0 + tx * 4 + j;
            s[i][j] = (gj <= gi) ? s[i][j] * vm[j] : 0.f;
          }
        }
      } else {
#pragma unroll
        for (int i = 0; i < 8; i++)
#pragma unroll
          for (int j = 0; j < 4; j++) s[i][j] *= vm[j];
      }
#pragma unroll
      for (int i = 0; i < 8; i++)
        *(float4*)&Ps[(ty * 8 + i) * PS_STRIDE + tx * 4] =
            make_float4(s[i][0], s[i][1], s[i][2], s[i][3]);
      __syncthreads();

      // O += P V (tile)
#pragma unroll 4
      for (int j = 0; j < 64; j++) {
        float p[8], bb[4];
#pragma unroll
        for (int i = 0; i < 8; i++) p[i] = Ps[(ty * 8 + i) * PS_STRIDE + j];
        *(float4*)&bb[0] = *(const float4*)&Vs[j * VS_STRIDE + tx * 4];
#pragma unroll
        for (int i = 0; i < 8; i++)
#pragma unroll
          for (int jj = 0; jj < 4; jj++) O[i][jj] = fmaf(p[i], bb[jj], O[i][jj]);
      }
    }
  }

  // Reduce Z across the 16 tx lanes sharing each row group
#pragma unroll
  for (int i = 0; i < 8; i++) {
    float z = Zacc[i];
    z += __shfl_xor_sync(0xffffffffu, z, 1);
    z += __shfl_xor_sync(0xffffffffu, z, 2);
    z += __shfl_xor_sync(0xffffffffu, z, 4);
    z += __shfl_xor_sync(0xffffffffu, z, 8);
    Zacc[i] = z;
  }

  // Epilogue: out[b,l,h,d] = qmask * O / Z  (concat-heads layout == (B,L,V))
#pragma unroll
  for (int i = 0; i < 8; i++) {
    int gi = i0 + ty * 8 + i;
    float f = qmask[b * L_ + gi] / Zacc[i];
    float4 v = make_float4(O[i][0] * f, O[i][1] * f, O[i][2] * f, O[i][3] * f);
    *(float4*)&Xg[((size_t)(b * L_ + gi) * H_ + h) * D_ + tx * 4] = v;
  }
}

// ---------------------------------------------------------------------------
// Residual add + LayerNorm over last dim (V=1024). One block per row.
// ---------------------------------------------------------------------------
__global__ __launch_bounds__(256) void add_ln(const float* __restrict__ X,
                                              const float* __restrict__ Qin,
                                              const float* __restrict__ gamma,
                                              const float* __restrict__ beta,
                                              float* __restrict__ out) {
  __shared__ float red[16];
  __shared__ float s_mean, s_rstd;
  const int row = blockIdx.x;
  const int t = threadIdx.x;
  const float4 xv = ((const float4*)(X + (size_t)row * V_))[t];
  const float4 qv = ((const float4*)(Qin + (size_t)row * V_))[t];
  float4 y = make_float4(xv.x + qv.x, xv.y + qv.y, xv.z + qv.z, xv.w + qv.w);
  float s = y.x + y.y + y.z + y.w;
  float ss = y.x * y.x + y.y * y.y + y.z * y.z + y.w * y.w;
#pragma unroll
  for (int o = 16; o; o >>= 1) {
    s += __shfl_xor_sync(0xffffffffu, s, o);
    ss += __shfl_xor_sync(0xffffffffu, ss, o);
  }
  if ((t & 31) == 0) { red[t >> 5] = s; red[8 + (t >> 5)] = ss; }
  __syncthreads();
  if (t < 32) {
    float s2 = (t < 8) ? red[t] : 0.f;
    float ss2 = (t < 8) ? red[8 + t] : 0.f;
#pragma unroll
    for (int o = 4; o; o >>= 1) {
      s2 += __shfl_xor_sync(0xffffffffu, s2, o);
      ss2 += __shfl_xor_sync(0xffffffffu, ss2, o);
    }
    if (t == 0) {
      float mean = s2 * (1.f / V_);
      float var = ss2 * (1.f / V_) - mean * mean;
      s_mean = mean;
      s_rstd = rsqrtf(var + 1e-3f);
    }
  }
  __syncthreads();
  float mean = s_mean, r = s_rstd;
  float4 g = ((const float4*)gamma)[t];
  float4 be = ((const float4*)beta)[t];
  float4 o4 = make_float4((y.x - mean) * r * g.x + be.x,
                          (y.y - mean) * r * g.y + be.y,
                          (y.z - mean) * r * g.z + be.z,
                          (y.w - mean) * r * g.w + be.w);
  ((float4*)(out + (size_t)row * V_))[t] = o4;
}

// ---------------------------------------------------------------------------
extern "C" void kernel_launch(void* const* d_in, const int* in_sizes, int n_in,
                              void* d_out, int out_size) {
  (void)in_sizes; (void)n_in; (void)out_size;
  const float* query = (const float*)d_in[0];
  const float* key   = (const float*)d_in[1];
  const float* value = (const float*)d_in[2];
  const float* qmask = (const float*)d_in[3];
  const float* vmask = (const float*)d_in[4];
  const float* Wq    = (const float*)d_in[5];
  const float* Wk    = (const float*)d_in[6];
  const float* Wv    = (const float*)d_in[7];
  const float* gamma = (const float*)d_in[8];
  const float* beta  = (const float*)d_in[9];
  float* out = (float*)d_out;

  float *gQ, *gK, *gV, *gX;
  cudaGetSymbolAddress((void**)&gQ, g_Q);
  cudaGetSymbolAddress((void**)&gK, g_K);
  cudaGetSymbolAddress((void**)&gV, g_V);
  cudaGetSymbolAddress((void**)&gX, g_X);

  const size_t fa_smem =
      (size_t)(64 * QT_STRIDE + 64 * KT_STRIDE + 64 * VS_STRIDE +
               128 * PS_STRIDE) * sizeof(float);  // 103424 B
  cudaFuncSetAttribute(flash_attn, cudaFuncAttributeMaxDynamicSharedMemorySize,
                       (int)fa_smem);

  dim3 gproj(M_ / 128, V_ / 128, 3);  // 32 x 8 x 3
  proj_gemm3<<<gproj, 256>>>(query, key, value, Wq, Wk, Wv, gQ, gK, gV);

  dim3 gfa(L_ / BM, B_ * H_);         // 16 x 32
  flash_attn<<<gfa, 256, fa_smem>>>(gQ, gK, gV, qmask, vmask, gX);

  add_ln<<<M_, 256>>>(gX, query, gamma, beta, out);
}